// round 1
// baseline (speedup 1.0000x reference)
#include <cuda_runtime.h>

// Shapes (fixed by the problem)
#define TT 64
#define BB 128
#define HH 200

// Scratch (no cudaMalloc allowed -> __device__ globals)
__device__ float g_cur[(size_t)TT * 9 * BB * HH];   // [t][branch(9)][b][h]  59 MB
__device__ float g_zsum[(size_t)TT * BB * HH];      // [t][b][h]             6.5 MB

// ---------------------------------------------------------------------------
// Kernel 1: 9 fused GEMMs.  cur[t, g, b, h] = sum_q x_slice[t,b,c,q] * W[c,h,q] + bias[c,h]
//   g = p*3 + c,  p in {L,M,R} selects column slice of x and weight matrix.
//   Block tile: 64 rows (t*B) x 200 cols (H), 200 threads (8 x 25), 8x8 per-thread tile.
//   Strided per-thread tiles -> conflict-free scalar LDS (A broadcast, B unique banks).
// ---------------------------------------------------------------------------
__global__ __launch_bounds__(200, 2)
void gemm_kernel(const float* __restrict__ x,
                 const float* __restrict__ WL, const float* __restrict__ bL,
                 const float* __restrict__ WM, const float* __restrict__ bM,
                 const float* __restrict__ WR, const float* __restrict__ bR)
{
    const int g = blockIdx.z;      // 0..8
    const int p = g / 3;           // 0=L, 1=M, 2=R
    const int c = g - p * 3;       // channel

    int width, off, K;
    const float* W;
    const float* bias;
    if (p == 0)      { width = 10; off = 0;  K = 320; W = WL; bias = bL; }
    else if (p == 1) { width = 12; off = 10; K = 384; W = WM; bias = bM; }
    else             { width = 10; off = 22; K = 320; W = WR; bias = bR; }

    __shared__ int   colmap[384];
    __shared__ float As[2][16 * 68];    // [kk][m], stride 68 (pad)
    __shared__ float Ws[2][16 * 204];   // [kk][n], stride 204 (pad)

    const int tid  = threadIdx.x;
    const int ty   = tid / 25;          // 0..7  (m groups)
    const int tx   = tid - ty * 25;     // 0..24 (n groups)
    const int row0 = blockIdx.x * 64;   // global row = t*128 + b

    // q = fs*width + l  ->  x column = fs*32 + off + l
    for (int q = tid; q < K; q += 200)
        colmap[q] = (q / width) * 32 + off + (q % width);
    __syncthreads();

    const float* xc = x + (size_t)c * 1024;            // + row*3072 + col
    const float* Wc = W + (size_t)c * 200 * K;         // [h][q]

    float acc[8][8];
    #pragma unroll
    for (int i = 0; i < 8; i++)
        #pragma unroll
        for (int j = 0; j < 8; j++) acc[i][j] = 0.f;

    const int nst = K / 16;

    // stage 0 load
    for (int idx = tid; idx < 64 * 16; idx += 200) {
        int kk = idx & 15, m = idx >> 4;
        As[0][kk * 68 + m] = xc[(size_t)(row0 + m) * 3072 + colmap[kk]];
    }
    for (int idx = tid; idx < 200 * 16; idx += 200) {
        int kk = idx & 15, n = idx >> 4;
        Ws[0][kk * 204 + n] = Wc[(size_t)n * K + kk];
    }
    __syncthreads();

    for (int s = 0; s < nst; s++) {
        const int cb = s & 1;
        if (s + 1 < nst) {
            const int nb = cb ^ 1;
            const int k0 = (s + 1) * 16;
            for (int idx = tid; idx < 64 * 16; idx += 200) {
                int kk = idx & 15, m = idx >> 4;
                As[nb][kk * 68 + m] = xc[(size_t)(row0 + m) * 3072 + colmap[k0 + kk]];
            }
            for (int idx = tid; idx < 200 * 16; idx += 200) {
                int kk = idx & 15, n = idx >> 4;
                Ws[nb][kk * 204 + n] = Wc[(size_t)n * K + k0 + kk];
            }
        }
        #pragma unroll
        for (int kk = 0; kk < 16; kk++) {
            float a[8], b[8];
            #pragma unroll
            for (int i = 0; i < 8; i++) a[i] = As[cb][kk * 68 + ty + 8 * i];
            #pragma unroll
            for (int j = 0; j < 8; j++) b[j] = Ws[cb][kk * 204 + tx + 25 * j];
            #pragma unroll
            for (int i = 0; i < 8; i++)
                #pragma unroll
                for (int j = 0; j < 8; j++)
                    acc[i][j] = fmaf(a[i], b[j], acc[i][j]);
        }
        __syncthreads();
    }

    // epilogue: rows row0 + ty + 8i, cols tx + 25j; add bias
    #pragma unroll
    for (int i = 0; i < 8; i++) {
        const int r = row0 + ty + 8 * i;
        const int t = r >> 7;        // r / 128
        const int b = r & 127;
        float* dst = &g_cur[(((size_t)t * 9 + g) * BB + b) * HH];
        #pragma unroll
        for (int j = 0; j < 8; j++) {
            const int h = tx + 25 * j;
            dst[h] = acc[i][j] + bias[c * 200 + h];
        }
    }
}

// ---------------------------------------------------------------------------
// Kernel 2: hidden LIF scan. One thread per (b,h), 9 branch states in regs,
// 64 timesteps, cur prefetch double-buffered. Writes z_sum[t,b,h].
// ---------------------------------------------------------------------------
__global__ __launch_bounds__(200)
void hidden_scan_kernel()
{
    const int b = blockIdx.x;
    const int h = threadIdx.x;

    float v[9], cc[9];
    #pragma unroll
    for (int br = 0; br < 9; br++) { v[br] = 0.f; cc[br] = 0.f; }

    const float* base = g_cur + (size_t)b * HH + h;   // + (t*9+br)*25600
    float cbuf[2][9];
    #pragma unroll
    for (int br = 0; br < 9; br++)
        cbuf[0][br] = base[(size_t)br * (BB * HH)];

    for (int t = 0; t < TT; t++) {
        const int cb = t & 1;
        if (t + 1 < TT) {
            #pragma unroll
            for (int br = 0; br < 9; br++)
                cbuf[cb ^ 1][br] = base[(size_t)((t + 1) * 9 + br) * (BB * HH)];
        }
        float zs = 0.f;
        #pragma unroll
        for (int br = 0; br < 9; br++) {
            float vd = v[br] + 0.1f * (cc[br] - v[br]);   // v + dt/tau_m * (i - v)
            float z  = (vd > 1.0f) ? 1.0f : 0.0f;          // heaviside(vd - 1)
            zs += z;
            v[br]  = (vd > 1.0f) ? 0.0f : vd;              // (1-z)*vd
            cc[br] = 0.8f * cc[br] + cbuf[cb][br];         // i*(1-dt/tau_s) + cur
        }
        g_zsum[((size_t)t * BB + b) * HH + h] = zs;
    }
}

// ---------------------------------------------------------------------------
// Kernel 3: output GEMM (time-parallel) + LI scan + volt, one block per b.
// ---------------------------------------------------------------------------
__global__ __launch_bounds__(256)
void output_kernel(const float* __restrict__ Wout,
                   const float* __restrict__ bout,
                   float* __restrict__ out)
{
    __shared__ float wo[2000];        // Wout[k][o][j] flat
    __shared__ float bo[40];          // bout[k][o]
    __shared__ float zs[16 * 200];    // 16-timestep chunk of z_sum for this b
    __shared__ float curo[64 * 40];   // cur_o[t][k*10+o]

    const int b   = blockIdx.x;
    const int tid = threadIdx.x;

    for (int i = tid; i < 2000; i += 256) wo[i] = Wout[i];
    if (tid < 40) bo[tid] = bout[tid];

    for (int ch = 0; ch < 4; ch++) {
        __syncthreads();
        for (int i = tid; i < 16 * 200; i += 256) {
            const int tl = i / 200, hh = i - tl * 200;
            zs[i] = g_zsum[((size_t)(ch * 16 + tl) * BB + b) * HH + hh];
        }
        __syncthreads();
        for (int d = tid; d < 16 * 40; d += 256) {
            const int tl  = d / 40;
            const int rem = d - tl * 40;        // k*10 + o
            const int k   = rem / 10;
            const float* zp = &zs[tl * 200 + k * 50];
            const float* wp = &wo[rem * 50];
            float s = bo[rem];
            #pragma unroll
            for (int j = 0; j < 50; j++) s = fmaf(zp[j], wp[j], s);
            curo[(ch * 16 + tl) * 40 + rem] = s;
        }
    }
    __syncthreads();

    // LI readout scan: 10 threads, each owns one o with 4 k-states in regs.
    if (tid < 10) {
        const int o = tid;
        float vo[4] = {0.f, 0.f, 0.f, 0.f};
        float io[4] = {0.f, 0.f, 0.f, 0.f};
        for (int t = 0; t < TT; t++) {
            float s = 0.f;
            #pragma unroll
            for (int k = 0; k < 4; k++) {
                vo[k] = vo[k] + 0.1f * (io[k] - vo[k]);      // vo_n (uses old io)
                io[k] = 0.8f * io[k] + curo[t * 40 + k * 10 + o];
                s += vo[k];
            }
            out[((size_t)t * BB + b) * 10 + o] = s;          // sum_k vo_n
        }
    }
}

// ---------------------------------------------------------------------------
extern "C" void kernel_launch(void* const* d_in, const int* in_sizes, int n_in,
                              void* d_out, int out_size)
{
    const float* x    = (const float*)d_in[0];
    const float* WL   = (const float*)d_in[1];
    const float* bL   = (const float*)d_in[2];
    const float* WM   = (const float*)d_in[3];
    const float* bM   = (const float*)d_in[4];
    const float* WR   = (const float*)d_in[5];
    const float* bR   = (const float*)d_in[6];
    const float* Wout = (const float*)d_in[7];
    const float* bout = (const float*)d_in[8];
    float* out = (float*)d_out;

    dim3 gg(128, 1, 9);                       // 128 M-blocks x 9 (part,channel) GEMMs
    gemm_kernel<<<gg, 200>>>(x, WL, bL, WM, bM, WR, bR);
    hidden_scan_kernel<<<128, 200>>>();
    output_kernel<<<128, 256>>>(Wout, bout, out);
}

// round 3
// speedup vs baseline: 3.3471x; 3.3471x over previous
#include <cuda_runtime.h>
#include <cuda_fp16.h>
#include <cstdint>

#define TT 64
#define BB 128
#define HH 200
#define RROWS 8192      // T*B
#define KTOT 1024       // packed K per channel (320 L + 384 M + 320 R)

// ---------------------------------------------------------------------------
// Scratch (__device__ globals; no cudaMalloc allowed)
// ---------------------------------------------------------------------------
__device__ float g_cur[(size_t)TT * 9 * BB * HH];    // [t][g][b][h]
__device__ float g_zsum[(size_t)TT * BB * HH];       // [t][b][h]
__device__ __half g_Ah[(size_t)3 * RROWS * KTOT];    // hi fp16 split of x (K-packed)
__device__ __half g_Am[(size_t)3 * RROWS * KTOT];    // lo fp16 split
__device__ __half g_Bh[(size_t)3 * HH * KTOT];       // hi fp16 split of W
__device__ __half g_Bm[(size_t)3 * HH * KTOT];       // lo fp16 split

// ---------------------------------------------------------------------------
// PTX helpers (all plain-sm_103-compatible: mma.sync / ldmatrix / cp.async)
// ---------------------------------------------------------------------------
__device__ __forceinline__ uint32_t smem_u32(const void* p) {
    uint32_t a;
    asm("{ .reg .u64 t; cvta.to.shared.u64 t, %1; cvt.u32.u64 %0, t; }" : "=r"(a) : "l"(p));
    return a;
}

#define CP16(dst, src) \
    asm volatile("cp.async.cg.shared.global [%0], [%1], 16;" :: "r"(dst), "l"(src) : "memory")
#define CP_COMMIT() asm volatile("cp.async.commit_group;" ::: "memory")
#define CP_WAIT1()  asm volatile("cp.async.wait_group 1;" ::: "memory")

#define LDSM_X4(r, addr) \
    asm volatile("ldmatrix.sync.aligned.m8n8.x4.shared.b16 {%0,%1,%2,%3}, [%4];" \
        : "=r"((r)[0]), "=r"((r)[1]), "=r"((r)[2]), "=r"((r)[3]) : "r"(addr))
#define LDSM_X2(r, addr) \
    asm volatile("ldmatrix.sync.aligned.m8n8.x2.shared.b16 {%0,%1}, [%2];" \
        : "=r"((r)[0]), "=r"((r)[1]) : "r"(addr))

#define MMA16816(d, a, b) \
    asm volatile("mma.sync.aligned.m16n8k16.row.col.f32.f16.f16.f32 " \
        "{%0,%1,%2,%3},{%4,%5,%6,%7},{%8,%9},{%0,%1,%2,%3};" \
        : "+f"((d)[0]), "+f"((d)[1]), "+f"((d)[2]), "+f"((d)[3]) \
        : "r"((a)[0]), "r"((a)[1]), "r"((a)[2]), "r"((a)[3]), "r"((b)[0]), "r"((b)[1]))

// ---------------------------------------------------------------------------
// Kernel A: split x (fp32) -> 2x fp16, gathered into K-packed [c][row][1024]
// ---------------------------------------------------------------------------
__global__ void convert_x(const float* __restrict__ x)
{
    size_t idx = (size_t)blockIdx.x * 256 + threadIdx.x;
    if (idx >= (size_t)3 * RROWS * KTOT) return;
    int q = (int)(idx & 1023);
    size_t rc = idx >> 10;               // c*RROWS + row
    int row = (int)(rc % RROWS);
    int c   = (int)(rc / RROWS);

    int xcol;
    if (q < 320)      { int fs = q / 10;                  xcol = fs * 32 + (q - fs * 10); }
    else if (q < 704) { int qq = q - 320; int fs = qq / 12; xcol = fs * 32 + 10 + (qq - fs * 12); }
    else              { int qq = q - 704; int fs = qq / 10; xcol = fs * 32 + 22 + (qq - fs * 10); }

    float v = x[((size_t)row * 3 + c) * 1024 + xcol];
    __half ah = __float2half_rn(v);
    __half am = __float2half_rn(v - __half2float(ah));
    g_Ah[idx] = ah;
    g_Am[idx] = am;
}

// ---------------------------------------------------------------------------
// Kernel B: split weights into K-packed [c][h][1024] fp16 pairs
// ---------------------------------------------------------------------------
__global__ void convert_w(const float* __restrict__ WL, const float* __restrict__ WM,
                          const float* __restrict__ WR)
{
    int idx = blockIdx.x * 256 + threadIdx.x;
    if (idx >= 3 * HH * KTOT) return;
    int q  = idx & 1023;
    int ch = idx >> 10;                  // c*HH + h
    float v;
    if (q < 320)      v = WL[(size_t)ch * 320 + q];
    else if (q < 704) v = WM[(size_t)ch * 384 + (q - 320)];
    else              v = WR[(size_t)ch * 320 + (q - 704)];
    __half bh = __float2half_rn(v);
    __half bm = __float2half_rn(v - __half2float(bh));
    g_Bh[idx] = bh;
    g_Bm[idx] = bm;
}

// ---------------------------------------------------------------------------
// Kernel C: HMMA GEMM.  D[128 x 200] = sum over K of (ah+am)*(bh+bm) (3 terms).
//   grid = (64 t-tiles, 9 g);  block = 256 thr = 8 warps, 16 rows per warp.
//   K chunk = 32, double-buffered cp.async.  Smem rows padded to 40 halfs
//   (20 words, 20 mod 8 = 4 -> ldmatrix 8-row fetches partition all 32 banks).
// ---------------------------------------------------------------------------
#define KCH   32
#define ASTR  40                          // halfs per smem row (A and B)
#define OFF_AM 5120                       // halfs: 128*40
#define OFF_BH 10240
#define OFF_BM 18240                      // 10240 + 200*40
#define STAGE_HALFS 26240                 // total per stage
#define GEMM_SMEM (2 * STAGE_HALFS * 2)   // bytes = 104960

__global__ __launch_bounds__(256)
void gemm_mma(const float* __restrict__ bL, const float* __restrict__ bM,
              const float* __restrict__ bR)
{
    extern __shared__ __half sm[];
    const uint32_t smb = smem_u32(sm);
    const int tid = threadIdx.x, wid = tid >> 5, lane = tid & 31;
    const int t = blockIdx.x;
    const int g = blockIdx.y, p = g / 3, c = g - p * 3;
    const int Kp  = (p == 1) ? 384 : 320;
    const int q0  = (p == 0) ? 0 : ((p == 1) ? 320 : 704);
    const float* bias = ((p == 0) ? bL : ((p == 1) ? bM : bR)) + c * HH;
    const int nch = Kp / KCH;

    const size_t abase = ((size_t)c * RROWS + (size_t)t * 128) * KTOT + q0;
    const size_t bbase = (size_t)c * HH * KTOT + q0;
    const __half* As[2] = { g_Ah + abase, g_Am + abase };
    const __half* Bs[2] = { g_Bh + bbase, g_Bm + bbase };

    float acc[25][4];
    #pragma unroll
    for (int n = 0; n < 25; n++)
        #pragma unroll
        for (int j = 0; j < 4; j++) acc[n][j] = 0.f;

    auto load_stage = [&](int buf, int koff) {
        const uint32_t sb = smb + buf * (STAGE_HALFS * 2);
        #pragma unroll
        for (int s2 = 0; s2 < 2; s2++) {
            // A: 128 rows x 32 halfs (4 x 16B per row)
            for (int i = tid; i < 512; i += 256) {
                int row = i >> 2, seg = i & 3;
                uint32_t dst = sb + (s2 * OFF_AM + row * ASTR + seg * 8) * 2;
                CP16(dst, As[s2] + (size_t)row * KTOT + koff + seg * 8);
            }
            // B: 200 rows x 32 halfs
            for (int i = tid; i < 800; i += 256) {
                int row = i >> 2, seg = i & 3;
                uint32_t dst = sb + (OFF_BH + s2 * 8000 + row * ASTR + seg * 8) * 2;
                CP16(dst, Bs[s2] + (size_t)row * KTOT + koff + seg * 8);
            }
        }
    };

    load_stage(0, 0);
    CP_COMMIT();

    for (int ch = 0; ch < nch; ch++) {
        if (ch + 1 < nch) load_stage((ch + 1) & 1, (ch + 1) * KCH);
        CP_COMMIT();
        CP_WAIT1();
        __syncthreads();

        const uint32_t sb = smb + (ch & 1) * (STAGE_HALFS * 2);
        #pragma unroll
        for (int kk = 0; kk < 2; kk++) {
            uint32_t ah[4], am[4];
            // A frag addr: rows (lane&15) within warp's 16-row strip, k-col halves
            uint32_t aaddr = sb + ((wid * 16 + (lane & 15)) * ASTR + kk * 16 + (lane >> 4) * 8) * 2;
            LDSM_X4(ah, aaddr);
            LDSM_X4(am, aaddr + OFF_AM * 2);
            // B frag base addr (n-chunk 0)
            uint32_t baddr = sb + (OFF_BH + (lane & 7) * ASTR + kk * 16 + ((lane >> 3) & 1) * 8) * 2;
            #pragma unroll
            for (int n = 0; n < 25; n++) {
                uint32_t bh[2], bm[2];
                uint32_t ba = baddr + n * (8 * ASTR) * 2;
                LDSM_X2(bh, ba);
                LDSM_X2(bm, ba + 8000 * 2);
                MMA16816(acc[n], ah, bh);   // hh
                MMA16816(acc[n], ah, bm);   // h*m
                MMA16816(acc[n], am, bh);   // m*h
            }
        }
        __syncthreads();
    }

    // Epilogue: direct stores with bias (rows = b, tile == t)
    const int r0 = wid * 16 + (lane >> 2);
    float* dst = g_cur + ((size_t)t * 9 + g) * BB * HH;
    #pragma unroll
    for (int n = 0; n < 25; n++) {
        const int col = n * 8 + (lane & 3) * 2;
        const float b0 = bias[col], b1 = bias[col + 1];
        float2 v0 = { acc[n][0] + b0, acc[n][1] + b1 };
        float2 v1 = { acc[n][2] + b0, acc[n][3] + b1 };
        *(float2*)&dst[(size_t)r0 * HH + col]       = v0;
        *(float2*)&dst[(size_t)(r0 + 8) * HH + col] = v1;
    }
}

// ---------------------------------------------------------------------------
// Kernel 2: hidden LIF scan (validated in round 1)
// ---------------------------------------------------------------------------
__global__ __launch_bounds__(200)
void hidden_scan_kernel()
{
    const int b = blockIdx.x;
    const int h = threadIdx.x;

    float v[9], cc[9];
    #pragma unroll
    for (int br = 0; br < 9; br++) { v[br] = 0.f; cc[br] = 0.f; }

    const float* base = g_cur + (size_t)b * HH + h;
    float cbuf[2][9];
    #pragma unroll
    for (int br = 0; br < 9; br++)
        cbuf[0][br] = base[(size_t)br * (BB * HH)];

    for (int t = 0; t < TT; t++) {
        const int cb = t & 1;
        if (t + 1 < TT) {
            #pragma unroll
            for (int br = 0; br < 9; br++)
                cbuf[cb ^ 1][br] = base[(size_t)((t + 1) * 9 + br) * (BB * HH)];
        }
        float zs = 0.f;
        #pragma unroll
        for (int br = 0; br < 9; br++) {
            float vd = v[br] + 0.1f * (cc[br] - v[br]);
            float z  = (vd > 1.0f) ? 1.0f : 0.0f;
            zs += z;
            v[br]  = (vd > 1.0f) ? 0.0f : vd;
            cc[br] = 0.8f * cc[br] + cbuf[cb][br];
        }
        g_zsum[((size_t)t * BB + b) * HH + h] = zs;
    }
}

// ---------------------------------------------------------------------------
// Kernel 3: output GEMM + LI scan (validated in round 1)
// ---------------------------------------------------------------------------
__global__ __launch_bounds__(256)
void output_kernel(const float* __restrict__ Wout,
                   const float* __restrict__ bout,
                   float* __restrict__ out)
{
    __shared__ float wo[2000];
    __shared__ float bo[40];
    __shared__ float zs[16 * 200];
    __shared__ float curo[64 * 40];

    const int b   = blockIdx.x;
    const int tid = threadIdx.x;

    for (int i = tid; i < 2000; i += 256) wo[i] = Wout[i];
    if (tid < 40) bo[tid] = bout[tid];

    for (int ch = 0; ch < 4; ch++) {
        __syncthreads();
        for (int i = tid; i < 16 * 200; i += 256) {
            const int tl = i / 200, hh = i - tl * 200;
            zs[i] = g_zsum[((size_t)(ch * 16 + tl) * BB + b) * HH + hh];
        }
        __syncthreads();
        for (int d = tid; d < 16 * 40; d += 256) {
            const int tl  = d / 40;
            const int rem = d - tl * 40;
            const int k   = rem / 10;
            const float* zp = &zs[tl * 200 + k * 50];
            const float* wp = &wo[rem * 50];
            float s = bo[rem];
            #pragma unroll
            for (int j = 0; j < 50; j++) s = fmaf(zp[j], wp[j], s);
            curo[(ch * 16 + tl) * 40 + rem] = s;
        }
    }
    __syncthreads();

    if (tid < 10) {
        const int o = tid;
        float vo[4] = {0.f, 0.f, 0.f, 0.f};
        float io[4] = {0.f, 0.f, 0.f, 0.f};
        for (int t = 0; t < TT; t++) {
            float s = 0.f;
            #pragma unroll
            for (int k = 0; k < 4; k++) {
                vo[k] = vo[k] + 0.1f * (io[k] - vo[k]);
                io[k] = 0.8f * io[k] + curo[t * 40 + k * 10 + o];
                s += vo[k];
            }
            out[((size_t)t * BB + b) * 10 + o] = s;
        }
    }
}

// ---------------------------------------------------------------------------
extern "C" void kernel_launch(void* const* d_in, const int* in_sizes, int n_in,
                              void* d_out, int out_size)
{
    const float* x    = (const float*)d_in[0];
    const float* WL   = (const float*)d_in[1];
    const float* bL   = (const float*)d_in[2];
    const float* WM   = (const float*)d_in[3];
    const float* bM   = (const float*)d_in[4];
    const float* WR   = (const float*)d_in[5];
    const float* bR   = (const float*)d_in[6];
    const float* Wout = (const float*)d_in[7];
    const float* bout = (const float*)d_in[8];
    float* out = (float*)d_out;

    cudaFuncSetAttribute(gemm_mma, cudaFuncAttributeMaxDynamicSharedMemorySize, GEMM_SMEM);

    convert_w<<<(3 * HH * KTOT + 255) / 256, 256>>>(WL, WM, WR);
    convert_x<<<(int)(((size_t)3 * RROWS * KTOT + 255) / 256), 256>>>(x);
    gemm_mma<<<dim3(64, 9), 256, GEMM_SMEM>>>(bL, bM, bR);
    hidden_scan_kernel<<<128, 200>>>();
    output_kernel<<<128, 256>>>(Wout, bout, out);
}

// round 5
// speedup vs baseline: 4.5058x; 1.3462x over previous
#include <cuda_runtime.h>
#include <cuda_fp16.h>
#include <cstdint>

#define TT 64
#define BB 128
#define HH 200
#define RROWS 8192      // T*B
#define KTOT 1024       // packed K per channel (320 L + 384 M + 320 R)

// ---------------------------------------------------------------------------
// Scratch (__device__ globals; no cudaMalloc allowed)
// ---------------------------------------------------------------------------
__device__ float g_cur[(size_t)TT * 9 * BB * HH];    // [t][g][b][h]
__device__ __half g_Bh[(size_t)3 * HH * KTOT];       // hi fp16 split of W (K-packed)
__device__ __half g_Bm[(size_t)3 * HH * KTOT];       // lo fp16 split

// ---------------------------------------------------------------------------
// PTX helpers (plain sm_103-compatible: mma.sync / ldmatrix / cp.async)
// ---------------------------------------------------------------------------
__device__ __forceinline__ uint32_t smem_u32(const void* p) {
    uint32_t a;
    asm("{ .reg .u64 t; cvta.to.shared.u64 t, %1; cvt.u32.u64 %0, t; }" : "=r"(a) : "l"(p));
    return a;
}

#define CP16(dst, src) \
    asm volatile("cp.async.cg.shared.global [%0], [%1], 16;" :: "r"(dst), "l"(src) : "memory")
#define CP_COMMIT() asm volatile("cp.async.commit_group;" ::: "memory")
#define CP_WAIT1()  asm volatile("cp.async.wait_group 1;" ::: "memory")

#define LDSM_X4(r, addr) \
    asm volatile("ldmatrix.sync.aligned.m8n8.x4.shared.b16 {%0,%1,%2,%3}, [%4];" \
        : "=r"((r)[0]), "=r"((r)[1]), "=r"((r)[2]), "=r"((r)[3]) : "r"(addr))
#define LDSM_X2(r, addr) \
    asm volatile("ldmatrix.sync.aligned.m8n8.x2.shared.b16 {%0,%1}, [%2];" \
        : "=r"((r)[0]), "=r"((r)[1]) : "r"(addr))

#define MMA16816(d, a, b) \
    asm volatile("mma.sync.aligned.m16n8k16.row.col.f32.f16.f16.f32 " \
        "{%0,%1,%2,%3},{%4,%5,%6,%7},{%8,%9},{%0,%1,%2,%3};" \
        : "+f"((d)[0]), "+f"((d)[1]), "+f"((d)[2]), "+f"((d)[3]) \
        : "r"((a)[0]), "r"((a)[1]), "r"((a)[2]), "r"((a)[3]), "r"((b)[0]), "r"((b)[1]))

// ---------------------------------------------------------------------------
// Kernel B: split weights into K-packed [c][h][1024] fp16 pairs
// ---------------------------------------------------------------------------
__global__ void convert_w(const float* __restrict__ WL, const float* __restrict__ WM,
                          const float* __restrict__ WR)
{
    int idx = blockIdx.x * 256 + threadIdx.x;
    if (idx >= 3 * HH * KTOT) return;
    int q  = idx & 1023;
    int ch = idx >> 10;                  // c*HH + h
    float v;
    if (q < 320)      v = WL[(size_t)ch * 320 + q];
    else if (q < 704) v = WM[(size_t)ch * 384 + (q - 320)];
    else              v = WR[(size_t)ch * 320 + (q - 704)];
    __half bh = __float2half_rn(v);
    __half bm = __float2half_rn(v - __half2float(bh));
    g_Bh[idx] = bh;
    g_Bm[idx] = bm;
}

// ---------------------------------------------------------------------------
// Kernel C: HMMA GEMM with fused A split.
//   D[128 x 200] = sum over K of (ah+am)*(bh+bm) (3 terms: hh, hm, mh).
//   grid = (64 t-tiles, 9 g);  block = 256 thr = 8 warps, 16 rows per warp.
//   A: fp32 gathered float2 loads -> in-register fp16 split -> STS.
//   B: fp16 split pairs via cp.async (precomputed by convert_w).
//   K chunk = 32, double-buffered.  Smem rows padded to 40 halfs.
// ---------------------------------------------------------------------------
#define KCH   32
#define ASTR  40                          // halfs per smem row (A and B)
#define OFF_AM 5120                       // halfs: 128*40
#define OFF_BH 10240
#define STAGE_HALFS 26240
#define STAGE_BYTES (STAGE_HALFS * 2)     // 52480
#define GEMM_SMEM (2 * STAGE_BYTES)       // 104960

__global__ __launch_bounds__(256)
void gemm_mma(const float* __restrict__ x,
              const float* __restrict__ bL, const float* __restrict__ bM,
              const float* __restrict__ bR)
{
    extern __shared__ __half sm[];
    const uint32_t smb = smem_u32(sm);
    const int tid = threadIdx.x, wid = tid >> 5, lane = tid & 31;
    const int t = blockIdx.x;
    const int g = blockIdx.y, p = g / 3, c = g - p * 3;

    int Kp, q0, w, off;
    const float* bias;
    if (p == 0)      { Kp = 320; q0 = 0;   w = 10; off = 0;  bias = bL; }
    else if (p == 1) { Kp = 384; q0 = 320; w = 12; off = 10; bias = bM; }
    else             { Kp = 320; q0 = 704; w = 10; off = 22; bias = bR; }
    bias += c * HH;
    const int nch = Kp / KCH;

    const float* xc = x + (size_t)t * 128 * 3072 + (size_t)c * 1024;
    const size_t bbase = (size_t)c * HH * KTOT + q0;
    const __half* Bsrc[2] = { g_Bh + bbase, g_Bm + bbase };

    float acc[25][4];
    #pragma unroll
    for (int n = 0; n < 25; n++)
        #pragma unroll
        for (int j = 0; j < 4; j++) acc[n][j] = 0.f;

    // --- A: gathered fp32 float2 loads into regs (128 rows x 16 float2) ---
    // Packed-K is LOCAL to the part: ql = koff + j*2 in [0, Kp). Decompose ql
    // (NOT q0+ql!) into (group, within-group) since q0 is not a multiple of w.
    float2 areg[8];
    auto loadA = [&](int koff) {
        #pragma unroll
        for (int s = 0; s < 8; s++) {
            int i = tid + s * 256;            // 2048 float2 per stage
            int row = i >> 4, j = i & 15;
            int ql = koff + j * 2;            // local packed k (even)
            int grp = ql / w, l = ql - grp * w; // w even -> l even, l+1 < w
            areg[s] = *(const float2*)(xc + (size_t)row * 3072 + grp * 32 + off + l);
        }
    };
    auto stsA = [&](int buf) {
        __half* base = sm + buf * STAGE_HALFS;
        #pragma unroll
        for (int s = 0; s < 8; s++) {
            int i = tid + s * 256;
            int row = i >> 4, j = i & 15;
            float vx = areg[s].x, vy = areg[s].y;
            __half hx = __float2half_rn(vx), hy = __float2half_rn(vy);
            __half mx = __float2half_rn(vx - __half2float(hx));
            __half my = __float2half_rn(vy - __half2float(hy));
            int pos = row * ASTR + j * 2;
            *(__half2*)(base + pos)          = __halves2half2(hx, hy);
            *(__half2*)(base + OFF_AM + pos) = __halves2half2(mx, my);
        }
    };
    // --- B: cp.async fp16 pairs (200 rows x 4 x 16B per split) ---
    auto loadB = [&](int buf, int koff) {
        const uint32_t sb = smb + buf * STAGE_BYTES;
        #pragma unroll
        for (int s2 = 0; s2 < 2; s2++) {
            for (int i = tid; i < 800; i += 256) {
                int row = i >> 2, seg = i & 3;
                uint32_t dst = sb + (OFF_BH + s2 * 8000 + row * ASTR + seg * 8) * 2;
                CP16(dst, Bsrc[s2] + (size_t)row * KTOT + koff + seg * 8);
            }
        }
    };

    // prologue: stage 0
    loadA(0);
    loadB(0, 0);
    CP_COMMIT();
    stsA(0);

    for (int ch = 0; ch < nch; ch++) {
        if (ch + 1 < nch) {
            loadA((ch + 1) * KCH);           // LDGs overlap compute below
            loadB((ch + 1) & 1, (ch + 1) * KCH);
        }
        CP_COMMIT();
        CP_WAIT1();                           // B(ch) landed
        __syncthreads();                      // A(ch) STS visible

        const uint32_t sb = smb + (ch & 1) * STAGE_BYTES;
        #pragma unroll
        for (int kk = 0; kk < 2; kk++) {
            uint32_t ah[4], am[4];
            uint32_t aaddr = sb + ((wid * 16 + (lane & 15)) * ASTR + kk * 16 + (lane >> 4) * 8) * 2;
            LDSM_X4(ah, aaddr);
            LDSM_X4(am, aaddr + OFF_AM * 2);
            uint32_t baddr = sb + (OFF_BH + (lane & 7) * ASTR + kk * 16 + ((lane >> 3) & 1) * 8) * 2;
            #pragma unroll
            for (int n = 0; n < 25; n++) {
                uint32_t bh[2], bm[2];
                uint32_t ba = baddr + n * (8 * ASTR) * 2;
                LDSM_X2(bh, ba);
                LDSM_X2(bm, ba + 8000 * 2);
                MMA16816(acc[n], ah, bh);     // hh
                MMA16816(acc[n], ah, bm);     // h*m
                MMA16816(acc[n], am, bh);     // m*h
            }
        }
        if (ch + 1 < nch) stsA((ch + 1) & 1); // prior reads of that buf done pre-sync
        __syncthreads();                      // protect B buf (ch+1)&1 overwrite
    }

    // Epilogue: direct stores with bias (rows = b; tile index == t)
    const int r0 = wid * 16 + (lane >> 2);
    float* dst = g_cur + ((size_t)t * 9 + g) * BB * HH;
    #pragma unroll
    for (int n = 0; n < 25; n++) {
        const int col = n * 8 + (lane & 3) * 2;
        const float b0 = bias[col], b1 = bias[col + 1];
        float2 v0 = { acc[n][0] + b0, acc[n][1] + b1 };
        float2 v1 = { acc[n][2] + b0, acc[n][3] + b1 };
        *(float2*)&dst[(size_t)r0 * HH + col]       = v0;
        *(float2*)&dst[(size_t)(r0 + 8) * HH + col] = v1;
    }
}

// ---------------------------------------------------------------------------
// Kernel D: fused hidden LIF scan + output GEMM + LI readout.
//   One block per b.  Threads (h-quad 0..49, branch 0..8) = 450 active.
//   z_sum never leaves smem; out written directly.
// ---------------------------------------------------------------------------
__global__ __launch_bounds__(480)
void fused_scan_out(const float* __restrict__ Wout,
                    const float* __restrict__ bout,
                    float* __restrict__ out)
{
    __shared__ float wo[2000];       // Wout[k][o][j]
    __shared__ float bo_s[40];
    __shared__ float part[1800];     // z partials [br][200]
    __shared__ float zs[200];        // z_sum over branches
    __shared__ float curo[40];       // cur_o[k*10+o] for current t

    const int b   = blockIdx.x;
    const int tid = threadIdx.x;
    const bool scan_thr = tid < 450;
    const int h4 = scan_thr ? (tid % 50) : 0;
    const int br = scan_thr ? (tid / 50) : 0;

    for (int i = tid; i < 2000; i += 480) wo[i] = Wout[i];
    if (tid < 40) bo_s[tid] = bout[tid];

    // LIF state: one branch x 4 h per thread
    float4 v  = {0.f, 0.f, 0.f, 0.f};
    float4 cc = {0.f, 0.f, 0.f, 0.f};
    // LI readout state in threads 0..9
    float vo[4] = {0.f, 0.f, 0.f, 0.f};
    float io[4] = {0.f, 0.f, 0.f, 0.f};

    const float4* cur4 = (const float4*)g_cur;
    // element index: ((t*9+br)*128 + b)*200 + h4*4  ->  float4 index /4
    float4 cb[2];
    if (scan_thr) cb[0] = cur4[((size_t)br * BB + b) * 50 + h4];
    __syncthreads();

    for (int t = 0; t < TT; t++) {
        const float4 cin = cb[t & 1];
        if (scan_thr && t + 1 < TT)
            cb[(t + 1) & 1] = cur4[((size_t)((t + 1) * 9 + br) * BB + b) * 50 + h4];

        if (scan_thr) {
            float4 z;
            float vdx = v.x + 0.1f * (cc.x - v.x);
            float vdy = v.y + 0.1f * (cc.y - v.y);
            float vdz = v.z + 0.1f * (cc.z - v.z);
            float vdw = v.w + 0.1f * (cc.w - v.w);
            z.x = (vdx > 1.0f) ? 1.0f : 0.0f;  v.x = (vdx > 1.0f) ? 0.0f : vdx;
            z.y = (vdy > 1.0f) ? 1.0f : 0.0f;  v.y = (vdy > 1.0f) ? 0.0f : vdy;
            z.z = (vdz > 1.0f) ? 1.0f : 0.0f;  v.z = (vdz > 1.0f) ? 0.0f : vdz;
            z.w = (vdw > 1.0f) ? 1.0f : 0.0f;  v.w = (vdw > 1.0f) ? 0.0f : vdw;
            cc.x = 0.8f * cc.x + cin.x;
            cc.y = 0.8f * cc.y + cin.y;
            cc.z = 0.8f * cc.z + cin.z;
            cc.w = 0.8f * cc.w + cin.w;
            ((float4*)part)[br * 50 + h4] = z;
        }
        __syncthreads();

        if (tid < 50) {                       // reduce 9 branches
            float4 s = ((float4*)part)[tid];
            #pragma unroll
            for (int r = 1; r < 9; r++) {
                float4 q = ((float4*)part)[r * 50 + tid];
                s.x += q.x; s.y += q.y; s.z += q.z; s.w += q.w;
            }
            ((float4*)zs)[tid] = s;
        }
        __syncthreads();

        if (tid < 40) {                       // output GEMM: rem = k*10+o
            const int k = tid / 10;
            const float* zp = &zs[k * 50];
            const float* wp = &wo[tid * 50];
            float s = bo_s[tid];
            #pragma unroll
            for (int j = 0; j < 50; j++) s = fmaf(zp[j], wp[j], s);
            curo[tid] = s;
        }
        __syncthreads();

        if (tid < 10) {                       // LI readout
            float s = 0.f;
            #pragma unroll
            for (int k = 0; k < 4; k++) {
                vo[k] = vo[k] + 0.1f * (io[k] - vo[k]);
                io[k] = 0.8f * io[k] + curo[k * 10 + tid];
                s += vo[k];
            }
            out[((size_t)t * BB + b) * 10 + tid] = s;
        }
        // next-iter smem writes are fenced by the 3 bars above
    }
}

// ---------------------------------------------------------------------------
extern "C" void kernel_launch(void* const* d_in, const int* in_sizes, int n_in,
                              void* d_out, int out_size)
{
    const float* x    = (const float*)d_in[0];
    const float* WL   = (const float*)d_in[1];
    const float* bL   = (const float*)d_in[2];
    const float* WM   = (const float*)d_in[3];
    const float* bM   = (const float*)d_in[4];
    const float* WR   = (const float*)d_in[5];
    const float* bR   = (const float*)d_in[6];
    const float* Wout = (const float*)d_in[7];
    const float* bout = (const float*)d_in[8];
    float* out = (float*)d_out;

    cudaFuncSetAttribute(gemm_mma, cudaFuncAttributeMaxDynamicSharedMemorySize, GEMM_SMEM);

    convert_w<<<(3 * HH * KTOT + 255) / 256, 256>>>(WL, WM, WR);
    gemm_mma<<<dim3(64, 9), 256, GEMM_SMEM>>>(x, bL, bM, bR);
    fused_scan_out<<<128, 480>>>(Wout, bout, out);
}